// round 4
// baseline (speedup 1.0000x reference)
#include <cuda_runtime.h>
#include <cuda_bf16.h>
#include <math.h>

// ============================================================================
// Bayesian LSTM forward:  B=8192, T=256, IN=1, H=10
//   w = mu + softplus(rho)*eps  (sampled once)
//   x_proj[t] = x[t]*w_ih + b ; LSTM over T ; out = h_T @ lin_w^T + lin_b
//
// Strategy:
//   Kernel 1 (tiny): sample weights, prescale into exponent domain, pack into
//                    f32x2 pairs laid out per quad-lane.
//   Kernel 2: 4 lanes per batch element (row-split over gate index j, padded
//             10->12 so each lane owns exactly 3 j's for ALL 4 gate types).
//             Weights live in registers. Matvec uses fma.rn.f32x2.
//             Activations via ex2.approx + rcp.approx with fused reciprocals.
//             h broadcast = 10 shuffles/step within the quad.
// ============================================================================

#define IN_DIM 1
#define HDIM   10
#define TSTEPS 256
#define BATCH  8192

using u64 = unsigned long long;

// ---------------- packed f32x2 helpers ----------------
__device__ __forceinline__ u64 pack2(float lo, float hi) {
    u64 r; asm("mov.b64 %0, {%1, %2};" : "=l"(r) : "f"(lo), "f"(hi)); return r;
}
__device__ __forceinline__ void unpack2(u64 v, float& lo, float& hi) {
    asm("mov.b64 {%0, %1}, %2;" : "=f"(lo), "=f"(hi) : "l"(v));
}
__device__ __forceinline__ u64 ffma2(u64 a, u64 b, u64 c) {
    u64 d; asm("fma.rn.f32x2 %0, %1, %2, %3;" : "=l"(d) : "l"(a), "l"(b), "l"(c)); return d;
}
__device__ __forceinline__ float ex2a(float x) {
    float y; asm("ex2.approx.f32 %0, %1;" : "=f"(y) : "f"(x)); return y;
}
__device__ __forceinline__ float rcpa(float x) {
    float y; asm("rcp.approx.f32 %0, %1;" : "=f"(y) : "f"(x)); return y;
}

// ---------------- packed, prescaled sampled weights ----------------
// Layout: per quad-lane k (0..3), per hidden m (0..9), per local row r (0..2):
//   wif[k][m][r] = ( K1*w_hh[m][ j], K1*w_hh[m][10+j] )   j = 3k+r   (i,f)
//   wgo[k][m][r] = ( K2*w_hh[m][20+j], K1*w_hh[m][30+j] )            (g,o)
// K1 = -log2(e) (sigmoid gates), K2 = -2*log2(e) (tanh gate). j>=10 -> zeros.
__device__ u64  g_wif[4][10][3];
__device__ u64  g_wgo[4][10][3];
__device__ u64  g_xif[4][3], g_xgo[4][3];   // w_ih packed the same way
__device__ u64  g_bif[4][3], g_bgo[4][3];   // bias packed the same way
__device__ float g_linw[HDIM];
__device__ float g_linb;

#define K1C (-1.44269504088896341f)
#define K2C (-2.88539008177792681f)

__global__ void sample_pack_kernel(
    const float* __restrict__ w_ih_mu, const float* __restrict__ w_ih_rho,
    const float* __restrict__ w_hh_mu, const float* __restrict__ w_hh_rho,
    const float* __restrict__ b_mu,    const float* __restrict__ b_rho,
    const float* __restrict__ eps_ih,  const float* __restrict__ eps_hh,
    const float* __restrict__ eps_b,
    const float* __restrict__ lin_w,   const float* __restrict__ lin_b)
{
    __shared__ float s_wih[40];
    __shared__ float s_b[40];
    __shared__ float s_whh[10][40];
    int t = threadIdx.x;

    for (int g = t; g < 40; g += blockDim.x) {
        s_wih[g] = w_ih_mu[g] + log1pf(expf(w_ih_rho[g])) * eps_ih[g];
        s_b[g]   = b_mu[g]    + log1pf(expf(b_rho[g]))    * eps_b[g];
    }
    for (int idx = t; idx < 400; idx += blockDim.x) {
        int m = idx / 40, g = idx % 40;
        s_whh[m][g] = w_hh_mu[idx] + log1pf(expf(w_hh_rho[idx])) * eps_hh[idx];
    }
    __syncthreads();

    // pack recurrent weights (120 (k,m,r) cells)
    for (int idx = t; idx < 120; idx += blockDim.x) {
        int k = idx / 30, rem = idx % 30, m = rem / 3, r = rem % 3;
        int j = 3 * k + r;
        float wi = 0.f, wf = 0.f, wg = 0.f, wo = 0.f;
        if (j < HDIM) {
            wi = K1C * s_whh[m][j];
            wf = K1C * s_whh[m][10 + j];
            wg = K2C * s_whh[m][20 + j];
            wo = K1C * s_whh[m][30 + j];
        }
        g_wif[k][m][r] = pack2(wi, wf);
        g_wgo[k][m][r] = pack2(wg, wo);
    }
    // pack input weights + bias (12 (k,r) cells)
    if (t < 12) {
        int k = t / 3, r = t % 3;
        int j = 3 * k + r;
        float xi = 0.f, xf = 0.f, xg = 0.f, xo = 0.f;
        float bi = 0.f, bf = 0.f, bg = 0.f, bo = 0.f;
        if (j < HDIM) {
            xi = K1C * s_wih[j];      xf = K1C * s_wih[10 + j];
            xg = K2C * s_wih[20 + j]; xo = K1C * s_wih[30 + j];
            bi = K1C * s_b[j];        bf = K1C * s_b[10 + j];
            bg = K2C * s_b[20 + j];   bo = K1C * s_b[30 + j];
        }
        g_xif[k][r] = pack2(xi, xf);
        g_xgo[k][r] = pack2(xg, xo);
        g_bif[k][r] = pack2(bi, bf);
        g_bgo[k][r] = pack2(bg, bo);
    }
    if (t < HDIM) g_linw[t] = lin_w[t];
    if (t == 0)   g_linb = lin_b[0];
}

// ---------------- main LSTM kernel ----------------
// 4 threads per batch element. Lane k owns gate rows j = 3k..3k+2 (j>=10 dummy,
// all-zero weights -> c stays 0, h stays 0). Each lane computes i,f,g,o for its
// rows, updates c/h locally, then the quad broadcasts the 10 h values.
__global__ void __launch_bounds__(64) lstm_fwd_kernel(
    const float* __restrict__ x, float* __restrict__ out)
{
    const int tid   = blockIdx.x * 64 + threadIdx.x;
    const int elem  = tid >> 2;
    const int lane  = threadIdx.x & 31;
    const int lane4 = lane & 3;
    const int qbase = lane & ~3;

    // ---- weights into registers ----
    u64 wif[10][3], wgo[10][3];
#pragma unroll
    for (int m = 0; m < 10; m++)
#pragma unroll
        for (int r = 0; r < 3; r++) {
            wif[m][r] = g_wif[lane4][m][r];
            wgo[m][r] = g_wgo[lane4][m][r];
        }
    u64 xif[3], xgo[3], bif[3], bgo[3];
#pragma unroll
    for (int r = 0; r < 3; r++) {
        xif[r] = g_xif[lane4][r];
        xgo[r] = g_xgo[lane4][r];
        bif[r] = g_bif[lane4][r];
        bgo[r] = g_bgo[lane4][r];
    }

    float h_all[10];
#pragma unroll
    for (int m = 0; m < 10; m++) h_all[m] = 0.f;
    float c[3]    = {0.f, 0.f, 0.f};
    float hown[3] = {0.f, 0.f, 0.f};

    const float4* xp = reinterpret_cast<const float4*>(x + (size_t)elem * TSTEPS);

#pragma unroll 1
    for (int t4 = 0; t4 < TSTEPS / 4; t4++) {
        float4 xv = xp[t4];
        float xs[4] = {xv.x, xv.y, xv.z, xv.w};
#pragma unroll
        for (int s = 0; s < 4; s++) {
            const float xt = xs[s];
            const u64 xpk = pack2(xt, xt);

            // gates (already in exponent domain thanks to prescaled weights)
            u64 aif[3], ago[3];
#pragma unroll
            for (int r = 0; r < 3; r++) {
                aif[r] = ffma2(xpk, xif[r], bif[r]);
                ago[r] = ffma2(xpk, xgo[r], bgo[r]);
            }
#pragma unroll
            for (int m = 0; m < 10; m++) {
                const u64 hp = pack2(h_all[m], h_all[m]);
#pragma unroll
                for (int r = 0; r < 3; r++) {
                    aif[r] = ffma2(hp, wif[m][r], aif[r]);
                    ago[r] = ffma2(hp, wgo[m][r], ago[r]);
                }
            }

            // pointwise: i=1/(1+A), f=1/(1+F), g=(1-B)/(1+B), o=1/(1+C)
            //   i*g   = (1-B) / ((1+A)(1+B))          -> one rcp
            //   o*tanh(c) = (1-D) / ((1+C)(1+D))      -> one rcp, D=2^(K2*c)
#pragma unroll
            for (int r = 0; r < 3; r++) {
                float ai, af, ag, ao;
                unpack2(aif[r], ai, af);
                unpack2(ago[r], ag, ao);
                const float A = ex2a(ai);
                const float F = ex2a(af);
                const float B = ex2a(ag);
                const float C = ex2a(ao);
                const float ig = (1.f - B) * rcpa((1.f + A) * (1.f + B));
                const float f_ = rcpa(1.f + F);
                c[r] = fmaf(f_, c[r], ig);
                const float D = ex2a(K2C * c[r]);
                hown[r] = (1.f - D) * rcpa((1.f + C) * (1.f + D));
            }

            // broadcast h within the quad: h[m] owned by lane m/3, slot m%3
#pragma unroll
            for (int m = 0; m < 10; m++) {
                const int slot = m - (m / 3) * 3;  // m % 3 (compile-time)
                float v = (slot == 0) ? hown[0] : ((slot == 1) ? hown[1] : hown[2]);
                h_all[m] = __shfl_sync(0xffffffffu, v, qbase + m / 3);
            }
        }
    }

    if (lane4 == 0) {
        float acc = g_linb;
#pragma unroll
        for (int m = 0; m < 10; m++) acc = fmaf(h_all[m], g_linw[m], acc);
        out[elem] = acc;
    }
}

// ---------------- launch ----------------
extern "C" void kernel_launch(void* const* d_in, const int* in_sizes, int n_in,
                              void* d_out, int out_size)
{
    const float* x        = (const float*)d_in[0];
    const float* w_ih_mu  = (const float*)d_in[1];
    const float* w_ih_rho = (const float*)d_in[2];
    const float* w_hh_mu  = (const float*)d_in[3];
    const float* w_hh_rho = (const float*)d_in[4];
    const float* b_mu     = (const float*)d_in[5];
    const float* b_rho    = (const float*)d_in[6];
    const float* eps_ih   = (const float*)d_in[7];
    const float* eps_hh   = (const float*)d_in[8];
    const float* eps_b    = (const float*)d_in[9];
    const float* lin_w    = (const float*)d_in[10];
    const float* lin_b    = (const float*)d_in[11];
    float* out = (float*)d_out;

    sample_pack_kernel<<<1, 128>>>(w_ih_mu, w_ih_rho, w_hh_mu, w_hh_rho,
                                   b_mu, b_rho, eps_ih, eps_hh, eps_b,
                                   lin_w, lin_b);

    const int threads = 64;                         // 2 warps/block
    const int blocks  = (BATCH * 4) / threads;      // 512 blocks
    lstm_fwd_kernel<<<blocks, threads>>>(x, out);
}

// round 8
// speedup vs baseline: 1.0347x; 1.0347x over previous
#include <cuda_runtime.h>
#include <cuda_bf16.h>
#include <math.h>

// ============================================================================
// Bayesian LSTM forward:  B=8192, T=256, IN=1, H=10
//   w = mu + softplus(rho)*eps  (sampled once)
//   gates prescaled into exponent domain; c tracked in K2-scaled domain.
//
// R5 changes vs R4 (104us):
//   - fused single-rcp c-update (3 rcp/row -> 2)
//   - c kept as chat = K2*c, so D = ex2(chat) directly
//   - tree-split matvec accumulation (chain 11 -> 6)
//   - per-row shuffle interleave, matvec consumes earliest-shuffled h first
//   - 1-warp blocks for even per-SM warp balance (7/SM nearly uniform)
// ============================================================================

#define HDIM   10
#define TSTEPS 256
#define BATCH  8192

using u64 = unsigned long long;

// ---------------- packed f32x2 helpers ----------------
__device__ __forceinline__ u64 pack2(float lo, float hi) {
    u64 r; asm("mov.b64 %0, {%1, %2};" : "=l"(r) : "f"(lo), "f"(hi)); return r;
}
__device__ __forceinline__ void unpack2(u64 v, float& lo, float& hi) {
    asm("mov.b64 {%0, %1}, %2;" : "=f"(lo), "=f"(hi) : "l"(v));
}
__device__ __forceinline__ u64 ffma2(u64 a, u64 b, u64 c) {
    u64 d; asm("fma.rn.f32x2 %0, %1, %2, %3;" : "=l"(d) : "l"(a), "l"(b), "l"(c)); return d;
}
__device__ __forceinline__ u64 fmul2(u64 a, u64 b) {
    u64 d; asm("mul.rn.f32x2 %0, %1, %2;" : "=l"(d) : "l"(a), "l"(b)); return d;
}
__device__ __forceinline__ u64 fadd2(u64 a, u64 b) {
    u64 d; asm("add.rn.f32x2 %0, %1, %2;" : "=l"(d) : "l"(a), "l"(b)); return d;
}
__device__ __forceinline__ float ex2a(float x) {
    float y; asm("ex2.approx.f32 %0, %1;" : "=f"(y) : "f"(x)); return y;
}
__device__ __forceinline__ float rcpa(float x) {
    float y; asm("rcp.approx.f32 %0, %1;" : "=f"(y) : "f"(x)); return y;
}

// ---------------- packed, prescaled sampled weights ----------------
// per quad-lane k (0..3), per hidden m (0..9), per local row r (0..2):
//   wif[k][m][r] = ( K1*w_hh[m][ j], K1*w_hh[m][10+j] )   j = 3k+r   (i,f)
//   wgo[k][m][r] = ( K2*w_hh[m][20+j], K1*w_hh[m][30+j] )            (g,o)
// K1 = -log2(e) (sigmoid), K2 = -2*log2(e) (tanh). j>=10 -> zeros.
__device__ u64  g_wif[4][10][3];
__device__ u64  g_wgo[4][10][3];
__device__ u64  g_xif[4][3], g_xgo[4][3];
__device__ u64  g_bif[4][3], g_bgo[4][3];
__device__ float g_linw[HDIM];
__device__ float g_linb;

#define K1C (-1.44269504088896341f)
#define K2C (-2.88539008177792681f)

__global__ void sample_pack_kernel(
    const float* __restrict__ w_ih_mu, const float* __restrict__ w_ih_rho,
    const float* __restrict__ w_hh_mu, const float* __restrict__ w_hh_rho,
    const float* __restrict__ b_mu,    const float* __restrict__ b_rho,
    const float* __restrict__ eps_ih,  const float* __restrict__ eps_hh,
    const float* __restrict__ eps_b,
    const float* __restrict__ lin_w,   const float* __restrict__ lin_b)
{
    __shared__ float s_wih[40];
    __shared__ float s_b[40];
    __shared__ float s_whh[10][40];
    int t = threadIdx.x;

    for (int g = t; g < 40; g += blockDim.x) {
        s_wih[g] = w_ih_mu[g] + log1pf(expf(w_ih_rho[g])) * eps_ih[g];
        s_b[g]   = b_mu[g]    + log1pf(expf(b_rho[g]))    * eps_b[g];
    }
    for (int idx = t; idx < 400; idx += blockDim.x) {
        int m = idx / 40, g = idx % 40;
        s_whh[m][g] = w_hh_mu[idx] + log1pf(expf(w_hh_rho[idx])) * eps_hh[idx];
    }
    __syncthreads();

    for (int idx = t; idx < 120; idx += blockDim.x) {
        int k = idx / 30, rem = idx % 30, m = rem / 3, r = rem % 3;
        int j = 3 * k + r;
        float wi = 0.f, wf = 0.f, wg = 0.f, wo = 0.f;
        if (j < HDIM) {
            wi = K1C * s_whh[m][j];
            wf = K1C * s_whh[m][10 + j];
            wg = K2C * s_whh[m][20 + j];
            wo = K1C * s_whh[m][30 + j];
        }
        g_wif[k][m][r] = pack2(wi, wf);
        g_wgo[k][m][r] = pack2(wg, wo);
    }
    if (t < 12) {
        int k = t / 3, r = t % 3;
        int j = 3 * k + r;
        float xi = 0.f, xf = 0.f, xg = 0.f, xo = 0.f;
        float bi = 0.f, bf = 0.f, bg = 0.f, bo = 0.f;
        if (j < HDIM) {
            xi = K1C * s_wih[j];      xf = K1C * s_wih[10 + j];
            xg = K2C * s_wih[20 + j]; xo = K1C * s_wih[30 + j];
            bi = K1C * s_b[j];        bf = K1C * s_b[10 + j];
            bg = K2C * s_b[20 + j];   bo = K1C * s_b[30 + j];
        }
        g_xif[k][r] = pack2(xi, xf);
        g_xgo[k][r] = pack2(xg, xo);
        g_bif[k][r] = pack2(bi, bf);
        g_bgo[k][r] = pack2(bg, bo);
    }
    if (t < HDIM) g_linw[t] = lin_w[t];
    if (t == 0)   g_linb = lin_b[0];
}

// ---------------- main LSTM kernel ----------------
// 4 threads per batch element, lane k owns gate rows j = 3k..3k+2.
// Matvec consumes h in order (0,3,6,9, 1,4,7, 2,5,8) so the h values that were
// shuffled earliest are used first.
__global__ void __launch_bounds__(32) lstm_fwd_kernel(
    const float* __restrict__ x, float* __restrict__ out)
{
    const int tid   = blockIdx.x * 32 + threadIdx.x;
    const int elem  = tid >> 2;
    const int lane  = threadIdx.x & 31;
    const int lane4 = lane & 3;
    const int qbase = lane & ~3;

    // ---- weights into registers ----
    u64 wif[10][3], wgo[10][3];
#pragma unroll
    for (int m = 0; m < 10; m++)
#pragma unroll
        for (int r = 0; r < 3; r++) {
            wif[m][r] = g_wif[lane4][m][r];
            wgo[m][r] = g_wgo[lane4][m][r];
        }
    u64 xif[3], xgo[3], bif[3], bgo[3];
#pragma unroll
    for (int r = 0; r < 3; r++) {
        xif[r] = g_xif[lane4][r];
        xgo[r] = g_xgo[lane4][r];
        bif[r] = g_bif[lane4][r];
        bgo[r] = g_bgo[lane4][r];
    }

    float h_all[10];
#pragma unroll
    for (int m = 0; m < 10; m++) h_all[m] = 0.f;
    float chat[3] = {0.f, 0.f, 0.f};   // chat = K2 * c  (exponent-domain cell)
    float hown[3] = {0.f, 0.f, 0.f};

    // matvec consumption order: earliest-broadcast h first
    const int morder[10] = {0, 3, 6, 9, 1, 4, 7, 2, 5, 8};

    const float4* xp = reinterpret_cast<const float4*>(x + (size_t)elem * TSTEPS);

#pragma unroll 1
    for (int t4 = 0; t4 < TSTEPS / 4; t4++) {
        float4 xv = xp[t4];
        float xs[4] = {xv.x, xv.y, xv.z, xv.w};
#pragma unroll
        for (int s = 0; s < 4; s++) {
            const float xt = xs[s];
            const u64 xpk = pack2(xt, xt);

            // ---- gates: tree-split accumulation (two chains + combine) ----
            u64 aif0[3], ago0[3], aif1[3], ago1[3];
#pragma unroll
            for (int r = 0; r < 3; r++) {
                aif0[r] = ffma2(xpk, xif[r], bif[r]);
                ago0[r] = ffma2(xpk, xgo[r], bgo[r]);
            }
            {
                const int m0 = morder[0];
                const u64 hp0 = pack2(h_all[m0], h_all[m0]);
#pragma unroll
                for (int r = 0; r < 3; r++) {
                    aif1[r] = fmul2(hp0, wif[m0][r]);
                    ago1[r] = fmul2(hp0, wgo[m0][r]);
                }
            }
#pragma unroll
            for (int p = 1; p < 10; p++) {
                const int m = morder[p];
                const u64 hp = pack2(h_all[m], h_all[m]);
                if (p & 1) {
#pragma unroll
                    for (int r = 0; r < 3; r++) {
                        aif0[r] = ffma2(hp, wif[m][r], aif0[r]);
                        ago0[r] = ffma2(hp, wgo[m][r], ago0[r]);
                    }
                } else {
#pragma unroll
                    for (int r = 0; r < 3; r++) {
                        aif1[r] = ffma2(hp, wif[m][r], aif1[r]);
                        ago1[r] = ffma2(hp, wgo[m][r], ago1[r]);
                    }
                }
            }

            // ---- pointwise per row, shuffle each row's h right away ----
            // i = 1/(1+A), f = 1/(1+F), g = (1-B)/(1+B), o = 1/(1+C)
            // chat' = (chat*P + K2*(1-B)*Q) * rcp(Q*P),  P=(1+A)(1+B), Q=1+F
            // D = 2^chat' = e^{-2c};  h = (1-D) * rcp((1+C)(1+D))
#pragma unroll
            for (int r = 0; r < 3; r++) {
                float ai, af, ag, ao;
                unpack2(fadd2(aif0[r], aif1[r]), ai, af);
                unpack2(fadd2(ago0[r], ago1[r]), ag, ao);
                const float A = ex2a(ai);
                const float F = ex2a(af);
                const float B = ex2a(ag);
                const float C = ex2a(ao);
                const float P  = (1.f + A) * (1.f + B);
                const float Q  = 1.f + F;
                const float kg = fmaf(B, -K2C, K2C);      // K2*(1-B)
                const float num = fmaf(chat[r], P, kg * Q);
                chat[r] = num * rcpa(Q * P);
                const float D = ex2a(chat[r]);
                hown[r] = (1.f - D) * rcpa((1.f + C) * (1.f + D));

                // broadcast this row's h across the quad (m = 3k + r, k = 0..3)
#pragma unroll
                for (int k = 0; k < 4; k++) {
                    const int m = 3 * k + r;
                    if (m < HDIM)
                        h_all[m] = __shfl_sync(0xffffffffu, hown[r], qbase + k);
                }
            }
        }
    }

    if (lane4 == 0) {
        float acc = g_linb;
#pragma unroll
        for (int m = 0; m < 10; m++) acc = fmaf(h_all[m], g_linw[m], acc);
        out[elem] = acc;
    }
}

// ---------------- launch ----------------
extern "C" void kernel_launch(void* const* d_in, const int* in_sizes, int n_in,
                              void* d_out, int out_size)
{
    const float* x        = (const float*)d_in[0];
    const float* w_ih_mu  = (const float*)d_in[1];
    const float* w_ih_rho = (const float*)d_in[2];
    const float* w_hh_mu  = (const float*)d_in[3];
    const float* w_hh_rho = (const float*)d_in[4];
    const float* b_mu     = (const float*)d_in[5];
    const float* b_rho    = (const float*)d_in[6];
    const float* eps_ih   = (const float*)d_in[7];
    const float* eps_hh   = (const float*)d_in[8];
    const float* eps_b    = (const float*)d_in[9];
    const float* lin_w    = (const float*)d_in[10];
    const float* lin_b    = (const float*)d_in[11];
    float* out = (float*)d_out;

    sample_pack_kernel<<<1, 128>>>(w_ih_mu, w_ih_rho, w_hh_mu, w_hh_rho,
                                   b_mu, b_rho, eps_ih, eps_hh, eps_b,
                                   lin_w, lin_b);

    // 1-warp blocks: 1024 blocks over 148 SMs -> ~7 warps/SM, near-uniform
    lstm_fwd_kernel<<<BATCH * 4 / 32, 32>>>(x, out);
}

// round 9
// speedup vs baseline: 1.0850x; 1.0486x over previous
#include <cuda_runtime.h>
#include <cuda_bf16.h>
#include <math.h>

// ============================================================================
// Bayesian LSTM forward:  B=8192, T=256, IN=1, H=10
// R9: one lane per gate-row, 3 elements per warp (lanes 0-9 / 10-19 / 20-29,
//     lanes 30-31 idle).  2731 warps -> 4.6 warps/SMSP (was 1.73).
//     Per lane: 1 row x 4 gates, 20 u64 weights in registers, 20 ffma2/step.
//     Exponent-domain gates (validated math from R5, rel_err ~5e-7).
// ============================================================================

#define HDIM   10
#define TSTEPS 256
#define BATCH  8192

using u64 = unsigned long long;

// ---------------- packed f32x2 helpers ----------------
__device__ __forceinline__ u64 pack2(float lo, float hi) {
    u64 r; asm("mov.b64 %0, {%1, %2};" : "=l"(r) : "f"(lo), "f"(hi)); return r;
}
__device__ __forceinline__ void unpack2(u64 v, float& lo, float& hi) {
    asm("mov.b64 {%0, %1}, %2;" : "=f"(lo), "=f"(hi) : "l"(v));
}
__device__ __forceinline__ u64 ffma2(u64 a, u64 b, u64 c) {
    u64 d; asm("fma.rn.f32x2 %0, %1, %2, %3;" : "=l"(d) : "l"(a), "l"(b), "l"(c)); return d;
}
__device__ __forceinline__ u64 fmul2(u64 a, u64 b) {
    u64 d; asm("mul.rn.f32x2 %0, %1, %2;" : "=l"(d) : "l"(a), "l"(b)); return d;
}
__device__ __forceinline__ u64 fadd2(u64 a, u64 b) {
    u64 d; asm("add.rn.f32x2 %0, %1, %2;" : "=l"(d) : "l"(a), "l"(b)); return d;
}
__device__ __forceinline__ float ex2a(float x) {
    float y; asm("ex2.approx.f32 %0, %1;" : "=f"(y) : "f"(x)); return y;
}
__device__ __forceinline__ float rcpa(float x) {
    float y; asm("rcp.approx.f32 %0, %1;" : "=f"(y) : "f"(x)); return y;
}

// ---------------- packed, prescaled sampled weights ----------------
// Per gate-row j (0..9), per hidden m (0..9):
//   g_wif[j][m] = ( K1*w_hh[m][ j],   K1*w_hh[m][10+j] )   (i,f)
//   g_wgo[j][m] = ( K2*w_hh[m][20+j], K1*w_hh[m][30+j] )   (g,o)
// K1 = -log2(e) (sigmoid), K2 = -2*log2(e) (tanh).
__device__ u64  g_wif[10][10];
__device__ u64  g_wgo[10][10];
__device__ u64  g_xif[10], g_xgo[10];   // w_ih
__device__ u64  g_bif[10], g_bgo[10];   // bias
__device__ float g_linw[HDIM];
__device__ float g_linb;

#define K1C (-1.44269504088896341f)
#define K2C (-2.88539008177792681f)

__global__ void sample_pack_kernel(
    const float* __restrict__ w_ih_mu, const float* __restrict__ w_ih_rho,
    const float* __restrict__ w_hh_mu, const float* __restrict__ w_hh_rho,
    const float* __restrict__ b_mu,    const float* __restrict__ b_rho,
    const float* __restrict__ eps_ih,  const float* __restrict__ eps_hh,
    const float* __restrict__ eps_b,
    const float* __restrict__ lin_w,   const float* __restrict__ lin_b)
{
    __shared__ float s_wih[40];
    __shared__ float s_b[40];
    __shared__ float s_whh[10][40];
    int t = threadIdx.x;

    for (int g = t; g < 40; g += blockDim.x) {
        s_wih[g] = w_ih_mu[g] + log1pf(expf(w_ih_rho[g])) * eps_ih[g];
        s_b[g]   = b_mu[g]    + log1pf(expf(b_rho[g]))    * eps_b[g];
    }
    for (int idx = t; idx < 400; idx += blockDim.x) {
        int m = idx / 40, g = idx % 40;
        s_whh[m][g] = w_hh_mu[idx] + log1pf(expf(w_hh_rho[idx])) * eps_hh[idx];
    }
    __syncthreads();

    // recurrent weights: 100 (j,m) cells
    for (int idx = t; idx < 100; idx += blockDim.x) {
        int j = idx / 10, m = idx % 10;
        g_wif[j][m] = pack2(K1C * s_whh[m][j],      K1C * s_whh[m][10 + j]);
        g_wgo[j][m] = pack2(K2C * s_whh[m][20 + j], K1C * s_whh[m][30 + j]);
    }
    // input weights + bias: 10 rows
    if (t < 10) {
        int j = t;
        g_xif[j] = pack2(K1C * s_wih[j],      K1C * s_wih[10 + j]);
        g_xgo[j] = pack2(K2C * s_wih[20 + j], K1C * s_wih[30 + j]);
        g_bif[j] = pack2(K1C * s_b[j],        K1C * s_b[10 + j]);
        g_bgo[j] = pack2(K2C * s_b[20 + j],   K1C * s_b[30 + j]);
    }
    if (t < HDIM) g_linw[t] = lin_w[t];
    if (t == 0)   g_linb = lin_b[0];
}

// ---------------- main LSTM kernel ----------------
// 32-thread blocks; lanes [10g, 10g+10) handle batch element blockIdx.x*3+g.
// Each lane owns ONE gate-row j: computes i,f,g,o for j, updates c[j], h[j],
// then the 10-lane group broadcasts h via shfl.
__global__ void __launch_bounds__(32) lstm_fwd_kernel(
    const float* __restrict__ x, float* __restrict__ out)
{
    const int lane = threadIdx.x & 31;
    int grp  = lane / 10;                 // 0,1,2 real; 3 = idle lanes 30,31
    const bool idle = (grp >= 3);
    if (idle) grp = 2;                    // harmless aliases for idle lanes
    const int row  = idle ? 0 : (lane - grp * 10);
    const int gbase = grp * 10;           // shfl source base for this element

    int elem = blockIdx.x * 3 + grp;
    const bool valid = !idle && (elem < BATCH);
    if (elem >= BATCH) elem = BATCH - 1;  // clamp for safe loads

    // ---- weights into registers (20 u64 = 40 regs) ----
    u64 wif[10], wgo[10];
#pragma unroll
    for (int m = 0; m < 10; m++) {
        wif[m] = g_wif[row][m];
        wgo[m] = g_wgo[row][m];
    }
    const u64 xif = g_xif[row], xgo = g_xgo[row];
    const u64 bif = g_bif[row], bgo = g_bgo[row];

    float h_all[10];
#pragma unroll
    for (int m = 0; m < 10; m++) h_all[m] = 0.f;
    float chat = 0.f;                     // chat = K2 * c (exponent-domain cell)
    float hown = 0.f;

    const float4* xp = reinterpret_cast<const float4*>(x + (size_t)elem * TSTEPS);

#pragma unroll 1
    for (int t4 = 0; t4 < TSTEPS / 4; t4++) {
        float4 xv = xp[t4];
        float xs[4] = {xv.x, xv.y, xv.z, xv.w};
#pragma unroll
        for (int s = 0; s < 4; s++) {
            const float xt = xs[s];
            const u64 xpk = pack2(xt, xt);

            // ---- gates: tree-split packed matvec over m ----
            u64 a0if = ffma2(xpk, xif, bif);
            u64 a0go = ffma2(xpk, xgo, bgo);
            u64 a1if, a1go;
            {
                const u64 hp0 = pack2(h_all[0], h_all[0]);
                a1if = fmul2(hp0, wif[0]);
                a1go = fmul2(hp0, wgo[0]);
            }
#pragma unroll
            for (int m = 1; m < 10; m++) {
                const u64 hp = pack2(h_all[m], h_all[m]);
                if (m & 1) {
                    a0if = ffma2(hp, wif[m], a0if);
                    a0go = ffma2(hp, wgo[m], a0go);
                } else {
                    a1if = ffma2(hp, wif[m], a1if);
                    a1go = ffma2(hp, wgo[m], a1go);
                }
            }

            // ---- pointwise (exponent-domain, 5 ex2 + 2 rcp) ----
            // A=e^-zi, F=e^-zf, B=e^-2zg, C=e^-zo
            // chat' = (chat*P + K2*(1-B)*Q) * rcp(Q*P), P=(1+A)(1+B), Q=1+F
            // D=2^chat' = e^-2c';  h = (1-D)*rcp((1+C)(1+D))
            float ai, af, ag, ao;
            unpack2(fadd2(a0if, a1if), ai, af);
            unpack2(fadd2(a0go, a1go), ag, ao);
            const float A = ex2a(ai);
            const float F = ex2a(af);
            const float B = ex2a(ag);
            const float C = ex2a(ao);
            const float P  = (1.f + A) * (1.f + B);
            const float Q  = 1.f + F;
            const float kg = fmaf(B, -K2C, K2C);          // K2*(1-B)
            const float num = fmaf(chat, P, kg * Q);
            chat = num * rcpa(Q * P);
            const float D = ex2a(chat);
            hown = (1.f - D) * rcpa((1.f + C) * (1.f + D));

            // ---- broadcast the 10 h values within the 10-lane group ----
#pragma unroll
            for (int m = 0; m < 10; m++)
                h_all[m] = __shfl_sync(0xffffffffu, hown, gbase + m);
        }
    }

    if (valid && row == 0) {
        float acc = g_linb;
#pragma unroll
        for (int m = 0; m < 10; m++) acc = fmaf(h_all[m], g_linw[m], acc);
        out[elem] = acc;
    }
}

// ---------------- launch ----------------
extern "C" void kernel_launch(void* const* d_in, const int* in_sizes, int n_in,
                              void* d_out, int out_size)
{
    const float* x        = (const float*)d_in[0];
    const float* w_ih_mu  = (const float*)d_in[1];
    const float* w_ih_rho = (const float*)d_in[2];
    const float* w_hh_mu  = (const float*)d_in[3];
    const float* w_hh_rho = (const float*)d_in[4];
    const float* b_mu     = (const float*)d_in[5];
    const float* b_rho    = (const float*)d_in[6];
    const float* eps_ih   = (const float*)d_in[7];
    const float* eps_hh   = (const float*)d_in[8];
    const float* eps_b    = (const float*)d_in[9];
    const float* lin_w    = (const float*)d_in[10];
    const float* lin_b    = (const float*)d_in[11];
    float* out = (float*)d_out;

    sample_pack_kernel<<<1, 128>>>(w_ih_mu, w_ih_rho, w_hh_mu, w_hh_rho,
                                   b_mu, b_rho, eps_ih, eps_hh, eps_b,
                                   lin_w, lin_b);

    const int nblocks = (BATCH + 2) / 3;   // 2731 one-warp blocks
    lstm_fwd_kernel<<<nblocks, 32>>>(x, out);
}